// round 7
// baseline (speedup 1.0000x reference)
#include <cuda_runtime.h>
#include <cuda_fp16.h>
#include <math.h>
#include <stdint.h>

#define BZ 4
#define LZ 2048
#define WD 2048
#define NHD 32
#define HDM 64
#define MBSZ 16
#define NMBC 128
#define EPSC 1e-6f
#define ELEMS (BZ*LZ*WD)
#define KP 4096            // split-fp16 concatenated K (2*2048)
#define KTILES (KP/64)     // 64
#define NROWS_B 4224       // 2048 q + 2048 v + 32 lr + 96 pad

// ---------------- scratch (device globals; no allocation) ----------------
__device__ float g_xq[ELEMS];
__device__ float g_xv[ELEMS];
__device__ float g_XQ[ELEMS];
__device__ float g_XK[ELEMS];
__device__ float g_scan[ELEMS];
__device__ float g_lr[BZ*NHD*NMBC*MBSZ];
__device__ float g_lrraw[8192 * 32];
__device__ __half g_A_hf[(size_t)8192 * KP];     // [hi | lo]
__device__ __half g_B_hf[(size_t)NROWS_B * KP];  // [hi | hi]

// ---------------- PTX helpers ----------------
__device__ __forceinline__ uint32_t smem_u32(const void* p) {
    uint32_t a;
    asm("{ .reg .u64 t; cvta.to.shared.u64 t, %1; cvt.u32.u64 %0, t; }" : "=r"(a) : "l"(p));
    return a;
}
#define CPA16(d, s) asm volatile("cp.async.cg.shared.global [%0], [%1], 16;" :: "r"(d), "l"(s) : "memory")

__device__ __forceinline__ void ldsm_x4(uint32_t a, uint32_t& r0, uint32_t& r1, uint32_t& r2, uint32_t& r3) {
    asm volatile("ldmatrix.sync.aligned.m8n8.x4.shared.b16 {%0,%1,%2,%3}, [%4];"
                 : "=r"(r0), "=r"(r1), "=r"(r2), "=r"(r3) : "r"(a));
}
__device__ __forceinline__ void mma_f16(float* c, const uint32_t* a, const uint32_t* b) {
    asm volatile("mma.sync.aligned.m16n8k16.row.col.f32.f16.f16.f32 "
                 "{%0,%1,%2,%3}, {%4,%5,%6,%7}, {%8,%9}, {%0,%1,%2,%3};"
                 : "+f"(c[0]), "+f"(c[1]), "+f"(c[2]), "+f"(c[3])
                 : "r"(a[0]), "r"(a[1]), "r"(a[2]), "r"(a[3]), "r"(b[0]), "r"(b[1]));
}

// ---------------- split-fp16 helpers ----------------
__device__ __forceinline__ void splitf16(const float4& v, uint2& hi, uint2& lo) {
    __half2 h01 = __floats2half2_rn(v.x, v.y);
    __half2 h23 = __floats2half2_rn(v.z, v.w);
    float2 f01 = __half22float2(h01), f23 = __half22float2(h23);
    __half2 l01 = __floats2half2_rn(v.x - f01.x, v.y - f01.y);
    __half2 l23 = __floats2half2_rn(v.z - f23.x, v.w - f23.y);
    hi.x = *(uint32_t*)&h01; hi.y = *(uint32_t*)&h23;
    lo.x = *(uint32_t*)&l01; lo.y = *(uint32_t*)&l23;
}

// ---------------- A conversion ----------------
__global__ __launch_bounds__(256) void ttt_cvtA(const float* __restrict__ src)
{
    int t = blockIdx.x * 256 + threadIdx.x;
    float4 v = ((const float4*)src)[t];
    int r = t >> 9, c4 = t & 511;
    size_t base = (size_t)r * KP + (c4 << 2);
    uint2 hi, lo;
    splitf16(v, hi, lo);
    *(uint2*)(g_A_hf + base)        = hi;
    *(uint2*)(g_A_hf + base + 2048) = lo;
}

// ---------------- B conversion (3 sources + zero pad) ----------------
__global__ __launch_bounds__(256) void ttt_cvtB(const float* __restrict__ w0,
                                                const float* __restrict__ w1,
                                                const float* __restrict__ w2)
{
    int row = blockIdx.x >> 1;
    int half = blockIdx.x & 1;
    int tid = threadIdx.x;
    const float* srcp = nullptr;
    if (row < 2048) srcp = w0 + (size_t)row * 2048;
    else if (row < 4096) srcp = w1 + (size_t)(row - 2048) * 2048;
    else if (row < 4128) srcp = w2 + (size_t)(row - 4096) * 2048;
    float4 v = make_float4(0, 0, 0, 0);
    if (srcp) v = ((const float4*)srcp)[half * 256 + tid];
    size_t base = (size_t)row * KP + ((half * 256 + tid) << 2);
    uint2 hi, lo;
    splitf16(v, hi, lo);
    *(uint2*)(g_B_hf + base)        = hi;
    *(uint2*)(g_B_hf + base + 2048) = hi;
}

// ---------------- fp16 mma.sync GEMM, 3-stage cp.async pipeline ----------------
#define HS_STAGE 32768
__global__ __launch_bounds__(256) void ttt_hgemm(float* Cext, int fused)
{
    extern __shared__ char smem[];
    uint32_t sb = smem_u32(smem);
    const int tid = threadIdx.x;
    const int wid = tid >> 5, lane = tid & 31;
    const int m0 = blockIdx.y << 7;
    const int n0 = blockIdx.x << 7;
    const int mw = (wid >> 2) << 6;
    const int nw = (wid & 3) << 5;

    const __half* Ab = g_A_hf + (size_t)m0 * KP;
    const __half* Bb = g_B_hf + (size_t)n0 * KP;

    float acc[4][4][4];
#pragma unroll
    for (int i = 0; i < 4; i++)
#pragma unroll
        for (int j = 0; j < 4; j++)
#pragma unroll
            for (int q = 0; q < 4; q++) acc[i][j][q] = 0.0f;

    auto load_stage = [&](int s, int kt) {
        uint32_t sA = sb + s * HS_STAGE;
        uint32_t sB = sA + 16384;
#pragma unroll
        for (int i = 0; i < 4; i++) {
            int ck = tid + (i << 8);
            int row = ck >> 3, c = ck & 7;
            uint32_t soff = (uint32_t)(row << 7) + (((uint32_t)(c ^ (row & 7))) << 4);
            CPA16(sA + soff, (const char*)(Ab + (size_t)row * KP + kt * 64 + c * 8));
            CPA16(sB + soff, (const char*)(Bb + (size_t)row * KP + kt * 64 + c * 8));
        }
        asm volatile("cp.async.commit_group;" ::: "memory");
    };

    load_stage(0, 0);
    load_stage(1, 1);
    const int lr15 = lane & 15, lhi = lane >> 4;

    for (int kt = 0; kt < KTILES; kt++) {
        int s = kt % 3;
        if (kt < KTILES - 2) {
            asm volatile("cp.async.wait_group 1;" ::: "memory");
        } else {
            asm volatile("cp.async.wait_group 0;" ::: "memory");
        }
        __syncthreads();
        if (kt + 2 < KTILES) load_stage((kt + 2) % 3, kt + 2);

        uint32_t aBase = sb + s * HS_STAGE;
        uint32_t bBase = aBase + 16384;
#pragma unroll
        for (int ks = 0; ks < 4; ks++) {
            uint32_t af[4][4];
#pragma unroll
            for (int mt = 0; mt < 4; mt++) {
                int row = mw + mt * 16 + lr15;
                uint32_t ad = aBase + (row << 7) + ((uint32_t)((2 * ks + lhi) ^ (row & 7)) << 4);
                ldsm_x4(ad, af[mt][0], af[mt][1], af[mt][2], af[mt][3]);
            }
            uint32_t bf[4][2];
#pragma unroll
            for (int np = 0; np < 2; np++) {
                int row = nw + np * 16 + lr15;
                uint32_t bd = bBase + (row << 7) + ((uint32_t)((2 * ks + lhi) ^ (row & 7)) << 4);
                uint32_t r0, r1, r2, r3;
                ldsm_x4(bd, r0, r1, r2, r3);
                bf[np * 2][0] = r0;     bf[np * 2][1] = r2;
                bf[np * 2 + 1][0] = r1; bf[np * 2 + 1][1] = r3;
            }
#pragma unroll
            for (int mt = 0; mt < 4; mt++)
#pragma unroll
                for (int nt = 0; nt < 4; nt++)
                    mma_f16(acc[mt][nt], af[mt], bf[nt]);
        }
        __syncthreads();
    }

#pragma unroll
    for (int mt = 0; mt < 4; mt++) {
#pragma unroll
        for (int nt = 0; nt < 4; nt++) {
            int col = n0 + nw + nt * 8 + (lane & 3) * 2;
            int row = m0 + mw + mt * 16 + (lane >> 2);
            float2 va = make_float2(acc[mt][nt][0], acc[mt][nt][1]);
            float2 vb = make_float2(acc[mt][nt][2], acc[mt][nt][3]);
            if (!fused) {
                *(float2*)(Cext + (size_t)row * 2048 + col) = va;
                *(float2*)(Cext + (size_t)(row + 8) * 2048 + col) = vb;
            } else if (col < 2048) {
                *(float2*)(g_xq + (size_t)row * 2048 + col) = va;
                *(float2*)(g_xq + (size_t)(row + 8) * 2048 + col) = vb;
            } else if (col < 4096) {
                *(float2*)(g_xv + (size_t)row * 2048 + col - 2048) = va;
                *(float2*)(g_xv + (size_t)(row + 8) * 2048 + col - 2048) = vb;
            } else if (col < 4128) {
                *(float2*)(g_lrraw + (size_t)row * 32 + col - 4096) = va;
                *(float2*)(g_lrraw + (size_t)(row + 8) * 32 + col - 4096) = vb;
            }
        }
    }
}

// ---------------- lr sigmoid + relayout ----------------
__global__ __launch_bounds__(256) void ttt_lr_sig(const float* __restrict__ lrb)
{
    int idx = blockIdx.x * 256 + threadIdx.x;
    int bl = idx >> 5, h = idx & 31;
    float v = g_lrraw[idx];
    float sg = 1.0f / (1.0f + expf(-(v + lrb[h])));
    int b = bl >> 11, l = bl & (LZ - 1);
    g_lr[(((size_t)b * NHD + h) * NMBC + (l >> 4)) * MBSZ + (l & 15)] = sg * (1.0f / 64.0f);
}

// ---------------- causal dwconv + RoPE (vectorized weights, uniform l) ----------------
__global__ __launch_bounds__(256) void ttt_conv_rope(
    const float* __restrict__ cqw, const float* __restrict__ cqb,
    const float* __restrict__ ckw, const float* __restrict__ ckb)
{
    __shared__ float scs[32], ssn[32];
    int idx = blockIdx.x * 256 + threadIdx.x;
    int pr = idx & (WD / 2 - 1);
    int bl = idx >> 10;
    int l  = bl & (LZ - 1);
    int ch = pr * 2;

    if (threadIdx.x < 32) {
        float fr = (float)(l & 15) * exp2f(-(float)threadIdx.x * (13.2877123795f / 32.0f));
        sincosf(fr, &ssn[threadIdx.x], &scs[threadIdx.x]);
    }
    __syncthreads();

    float4 wq0 = ((const float4*)cqw)[ch];
    float4 wq1 = ((const float4*)cqw)[ch + 1];
    float4 wk0 = ((const float4*)ckw)[ch];
    float4 wk1 = ((const float4*)ckw)[ch + 1];
    float2 bq = ((const float2*)cqb)[pr];
    float2 bk = ((const float2*)ckb)[pr];

    const float2* xin = (const float2*)g_xq;
    float q0 = bq.x, q1 = bq.y, k0 = bk.x, k1 = bk.y;
    if (l >= 3) {   // block-uniform branch
        float2 v0 = xin[(size_t)(bl - 3) * (WD / 2) + pr];
        float2 v1 = xin[(size_t)(bl - 2) * (WD / 2) + pr];
        float2 v2 = xin[(size_t)(bl - 1) * (WD / 2) + pr];
        float2 v3 = xin[(size_t)bl * (WD / 2) + pr];
        q0 += v0.x * wq0.x + v1.x * wq0.y + v2.x * wq0.z + v3.x * wq0.w;
        q1 += v0.y * wq1.x + v1.y * wq1.y + v2.y * wq1.z + v3.y * wq1.w;
        k0 += v0.x * wk0.x + v1.x * wk0.y + v2.x * wk0.z + v3.x * wk0.w;
        k1 += v0.y * wk1.x + v1.y * wk1.y + v2.y * wk1.z + v3.y * wk1.w;
    } else {
        const float* wq0a = (const float*)&wq0;
        const float* wq1a = (const float*)&wq1;
        const float* wk0a = (const float*)&wk0;
        const float* wk1a = (const float*)&wk1;
#pragma unroll
        for (int k = 0; k < 4; k++) {
            if (l - 3 + k >= 0) {
                float2 v = xin[(size_t)(bl - 3 + k) * (WD / 2) + pr];
                q0 += v.x * wq0a[k];  q1 += v.y * wq1a[k];
                k0 += v.x * wk0a[k];  k1 += v.y * wk1a[k];
            }
        }
    }
    int i = (ch & 63) >> 1;
    float sn = ssn[i], cs = scs[i];
    ((float2*)g_XQ)[idx] = make_float2(q0 * cs - q1 * sn, q1 * cs + q0 * sn);
    ((float2*)g_XK)[idx] = make_float2(k0 * cs - k1 * sn, k1 * cs + k0 * sn);
}

// ---------------- the TTT scan: one block (512 threads) per (b,h) ----------------
__global__ __launch_bounds__(512) void ttt_scan_kernel(
    const float* __restrict__ lt_idx,
    const float* __restrict__ lnw_g, const float* __restrict__ lnb_g,
    const float* __restrict__ W1g,   const float* __restrict__ b1g)
{
    __shared__ float W1[64][64];
    __shared__ float sxq[16][68], sxk[16][68], sxv[16][68];
    __shared__ float grad[16][68], z[16][68];
    __shared__ float attn[16][16];
    __shared__ float b1[64], lnw[64], lnb[64], lr[16], tok[16];

    int tid = threadIdx.x;
    int b = blockIdx.x >> 5, h = blockIdx.x & 31;

    for (int o = tid; o < 4096; o += 512)
        ((float*)W1)[o] = W1g[(size_t)h * 4096 + o];
    if (tid < 64) {
        b1[tid]  = b1g[h * 64 + tid];
        lnw[tid] = lnw_g[h * 64 + tid];
        lnb[tid] = lnb_g[h * 64 + tid];
    }
    if (tid < 16) tok[tid] = fmaxf(1.0f / (float)(tid + 1) + lt_idx[tid], 0.0f);
    __syncthreads();

    const int warp = tid >> 5, lane = tid & 31;
    const int zc = lane * 2;               // column pair base for Z matmuls
    const size_t base = ((size_t)b * LZ) * WD + (size_t)h * HDM;
    const float te_last = tok[15];

    for (int n = 0; n < NMBC; n++) {
        // load tiles: warp r loads row r (float2 per lane)
        {
            size_t g0 = base + (size_t)(n * MBSZ + warp) * WD + zc;
            *(float2*)&sxq[warp][zc] = *(const float2*)&g_XQ[g0];
            *(float2*)&sxk[warp][zc] = *(const float2*)&g_XK[g0];
            *(float2*)&sxv[warp][zc] = *(const float2*)&g_xv[g0];
        }
        if (tid < 16) lr[tid] = g_lr[(((size_t)b * NHD + h) * NMBC + n) * MBSZ + tid];
        __syncthreads();

        // Z1 = xk @ W1 + b1 : warp r computes row r, lane computes cols zc,zc+1
        {
            float a0 = b1[zc], a1 = b1[zc + 1];
#pragma unroll 8
            for (int e = 0; e < 64; e++) {
                float xe = sxk[warp][e];
                float2 w = *(const float2*)&W1[e][zc];
                a0 += xe * w.x; a1 += xe * w.y;
            }
            z[warp][zc] = a0; z[warp][zc + 1] = a1;
        }
        // attn (threads 0..255)
        if (tid < 256) {
            int i = tid >> 4, j = tid & 15;
            float s = 0.0f;
#pragma unroll 8
            for (int d = 0; d < 64; d++) s += sxq[i][d] * sxk[j][d];
            attn[i][j] = s;
        }
        __syncwarp();

        // grad = ln_l2_bwd(Z1, xv-xk): warp r handles row r (own z row)
        {
            int r = warp;
            float x0 = z[r][lane], x1 = z[r][lane + 32];
            float s = x0 + x1;
#pragma unroll
            for (int o = 16; o; o >>= 1) s += __shfl_xor_sync(0xffffffffu, s, o);
            float mu = s * (1.0f / 64.0f);
            float e0 = x0 - mu, e1 = x1 - mu;
            float v = e0 * e0 + e1 * e1;
#pragma unroll
            for (int o = 16; o; o >>= 1) v += __shfl_xor_sync(0xffffffffu, v, o);
            float rstd = rsqrtf(v * (1.0f / 64.0f) + EPSC);
            float xh0 = e0 * rstd, xh1 = e1 * rstd;
            float t0 = sxv[r][lane] - sxk[r][lane];
            float t1 = sxv[r][lane + 32] - sxk[r][lane + 32];
            float gy0 = (lnw[lane] * xh0 + lnb[lane] - t0) * lnw[lane];
            float gy1 = (lnw[lane + 32] * xh1 + lnb[lane + 32] - t1) * lnw[lane + 32];
            float s1 = gy0 + gy1, s2 = gy0 * xh0 + gy1 * xh1;
#pragma unroll
            for (int o = 16; o; o >>= 1) {
                s1 += __shfl_xor_sync(0xffffffffu, s1, o);
                s2 += __shfl_xor_sync(0xffffffffu, s2, o);
            }
            float sc = rstd * (1.0f / 64.0f);
            grad[r][lane]      = (64.0f * gy0 - s1 - xh0 * s2) * sc;
            grad[r][lane + 32] = (64.0f * gy1 - s1 - xh1 * s2) * sc;
        }
        __syncthreads();

        // Z1_bar: warp r row r, lane cols zc,zc+1
        {
            float a0 = b1[zc], a1 = b1[zc + 1];
#pragma unroll 8
            for (int e = 0; e < 64; e++) {
                float xe = sxq[warp][e];
                float2 w = *(const float2*)&W1[e][zc];
                a0 += xe * w.x; a1 += xe * w.y;
            }
            float tk = tok[warp];
            for (int j = 0; j <= warp; j++) {
                float cf = tk * lr[j] * (attn[warp][j] + 1.0f);
                float2 gr = *(const float2*)&grad[j][zc];
                a0 -= cf * gr.x; a1 -= cf * gr.y;
            }
            z[warp][zc] = a0; z[warp][zc + 1] = a1;
        }
        __syncwarp();

        // out = xq + ln_fwd(Z1_bar): warp r row r
        {
            int r = warp;
            float x0 = z[r][lane], x1 = z[r][lane + 32];
            float s = x0 + x1;
#pragma unroll
            for (int o = 16; o; o >>= 1) s += __shfl_xor_sync(0xffffffffu, s, o);
            float mu = s * (1.0f / 64.0f);
            float e0 = x0 - mu, e1 = x1 - mu;
            float v = e0 * e0 + e1 * e1;
#pragma unroll
            for (int o = 16; o; o >>= 1) v += __shfl_xor_sync(0xffffffffu, v, o);
            float rstd = rsqrtf(v * (1.0f / 64.0f) + EPSC);
            size_t go = base + (size_t)(n * MBSZ + r) * WD;
            g_scan[go + lane]      = sxq[r][lane]      + lnw[lane] * (e0 * rstd)      + lnb[lane];
            g_scan[go + lane + 32] = sxq[r][lane + 32] + lnw[lane + 32] * (e1 * rstd) + lnb[lane + 32];
        }
        __syncthreads();   // Z1_bar readers done with W1/grad; now update state

        // W1 -= te*(lr*xk)^T @ grad : thread handles row d = tid>>3, cols c0..c0+7
        {
            int d = tid >> 3;
            int c0 = (tid & 7) * 8;
            float4 acc0 = *(const float4*)&W1[d][c0];
            float4 acc1 = *(const float4*)&W1[d][c0 + 4];
#pragma unroll
            for (int j = 0; j < 16; j++) {
                float cf = te_last * lr[j] * sxk[j][d];
                float4 g0 = *(const float4*)&grad[j][c0];
                float4 g1 = *(const float4*)&grad[j][c0 + 4];
                acc0.x -= cf * g0.x; acc0.y -= cf * g0.y; acc0.z -= cf * g0.z; acc0.w -= cf * g0.w;
                acc1.x -= cf * g1.x; acc1.y -= cf * g1.y; acc1.z -= cf * g1.z; acc1.w -= cf * g1.w;
            }
            *(float4*)&W1[d][c0] = acc0;
            *(float4*)&W1[d][c0 + 4] = acc1;
        }
        if (tid < 64) {
            float s = 0.0f;
#pragma unroll
            for (int j = 0; j < 16; j++) s += lr[j] * grad[j][tid];
            b1[tid] -= te_last * s;
        }
        __syncthreads();
    }
}

// ---------------- post layer-norm fused with A split-fp16 conversion ----------------
__global__ __launch_bounds__(256) void ttt_postnorm_cvt(
    const float* __restrict__ pw, const float* __restrict__ pb)
{
    __shared__ float red[8];
    int bl = blockIdx.x, tid = threadIdx.x;
    int lane = tid & 31, warp = tid >> 5;
    const float4* src = (const float4*)(g_scan + (size_t)bl * WD);
    float4 v0 = src[tid], v1 = src[tid + 256];

    float s = v0.x + v0.y + v0.z + v0.w + v1.x + v1.y + v1.z + v1.w;
#pragma unroll
    for (int o = 16; o; o >>= 1) s += __shfl_xor_sync(0xffffffffu, s, o);
    if (lane == 0) red[warp] = s;
    __syncthreads();
    float tot = 0.0f;
#pragma unroll
    for (int i = 0; i < 8; i++) tot += red[i];
    float mu = tot * (1.0f / 2048.0f);
    __syncthreads();

    float q =
        (v0.x - mu) * (v0.x - mu) + (v0.y - mu) * (v0.y - mu) +
        (v0.z - mu) * (v0.z - mu) + (v0.w - mu) * (v0.w - mu) +
        (v1.x - mu) * (v1.x - mu) + (v1.y - mu) * (v1.y - mu) +
        (v1.z - mu) * (v1.z - mu) + (v1.w - mu) * (v1.w - mu);
#pragma unroll
    for (int o = 16; o; o >>= 1) q += __shfl_xor_sync(0xffffffffu, q, o);
    if (lane == 0) red[warp] = q;
    __syncthreads();
    float qt = 0.0f;
#pragma unroll
    for (int i = 0; i < 8; i++) qt += red[i];
    float rstd = rsqrtf(qt * (1.0f / 2048.0f) + EPSC);

    float4 w0 = ((const float4*)pw)[tid], w1 = ((const float4*)pw)[tid + 256];
    float4 b0 = ((const float4*)pb)[tid], b1v = ((const float4*)pb)[tid + 256];
    float4 o0, o1;
    o0.x = (v0.x - mu) * rstd * w0.x + b0.x;
    o0.y = (v0.y - mu) * rstd * w0.y + b0.y;
    o0.z = (v0.z - mu) * rstd * w0.z + b0.z;
    o0.w = (v0.w - mu) * rstd * w0.w + b0.w;
    o1.x = (v1.x - mu) * rstd * w1.x + b1v.x;
    o1.y = (v1.y - mu) * rstd * w1.y + b1v.y;
    o1.z = (v1.z - mu) * rstd * w1.z + b1v.z;
    o1.w = (v1.w - mu) * rstd * w1.w + b1v.w;

    size_t base0 = (size_t)bl * KP + (tid << 2);
    size_t base1 = (size_t)bl * KP + ((tid + 256) << 2);
    uint2 hi, lo;
    splitf16(o0, hi, lo);
    *(uint2*)(g_A_hf + base0)        = hi;
    *(uint2*)(g_A_hf + base0 + 2048) = lo;
    splitf16(o1, hi, lo);
    *(uint2*)(g_A_hf + base1)        = hi;
    *(uint2*)(g_A_hf + base1 + 2048) = lo;
}

// ---------------- launcher ----------------
extern "C" void kernel_launch(void* const* d_in, const int* in_sizes, int n_in,
                              void* d_out, int out_size)
{
    const float* hs  = (const float*)d_in[0];
    const float* q_w = (const float*)d_in[1];
    const float* v_w = (const float*)d_in[2];
    const float* o_w = (const float*)d_in[3];
    const float* cqw = (const float*)d_in[4];
    const float* cqb = (const float*)d_in[5];
    const float* ckw = (const float*)d_in[6];
    const float* ckb = (const float*)d_in[7];
    const float* lrw = (const float*)d_in[8];
    const float* lrb = (const float*)d_in[9];
    const float* lti = (const float*)d_in[10];
    const float* tnw = (const float*)d_in[11];
    const float* tnb = (const float*)d_in[12];
    const float* W1i = (const float*)d_in[13];
    const float* b1i = (const float*)d_in[14];
    const float* pnw = (const float*)d_in[15];
    const float* pnb = (const float*)d_in[16];
    float* out = (float*)d_out;

    static int smem_set = 0;
    if (!smem_set) {
        cudaFuncSetAttribute(ttt_hgemm, cudaFuncAttributeMaxDynamicSharedMemorySize, 3 * HS_STAGE);
        smem_set = 1;
    }

    // fused QV+lr projection: A=hs, B=[q_w; v_w; lr_w; pad]
    ttt_cvtA<<<16384, 256>>>(hs);
    ttt_cvtB<<<2 * NROWS_B, 256>>>(q_w, v_w, lrw);
    ttt_hgemm<<<dim3(33, 64), 256, 3 * HS_STAGE>>>(nullptr, 1);   // -> g_xq, g_xv, g_lrraw

    ttt_conv_rope<<<(ELEMS / 2) / 256, 256>>>(cqw, cqb, ckw, ckb);
    ttt_lr_sig<<<1024, 256>>>(lrb);
    ttt_scan_kernel<<<BZ * NHD, 512>>>(lti, tnw, tnb, W1i, b1i);

    // B for final GEMM (stream-ordered after GEMM1 read g_B_hf)
    ttt_cvtB<<<2 * 2048, 256>>>(o_w, o_w, o_w);
    ttt_postnorm_cvt<<<BZ * LZ, 256>>>(pnw, pnb);                 // -> g_A_hf

    ttt_hgemm<<<dim3(16, 64), 256, 3 * HS_STAGE>>>(out, 0);
}

// round 8
// speedup vs baseline: 1.0808x; 1.0808x over previous
#include <cuda_runtime.h>
#include <cuda_fp16.h>
#include <math.h>
#include <stdint.h>

#define BZ 4
#define LZ 2048
#define WD 2048
#define NHD 32
#define HDM 64
#define MBSZ 16
#define NMBC 128
#define EPSC 1e-6f
#define ELEMS (BZ*LZ*WD)
#define KP 4096            // split-fp16 concatenated K (2*2048)
#define KTILES (KP/64)     // 64
#define NROWS_B 4224       // 2048 q + 2048 v + 32 lr + 96 pad

// ---------------- scratch (device globals; no allocation) ----------------
__device__ float g_xq[ELEMS];
__device__ float g_xv[ELEMS];
__device__ float g_XQ[ELEMS];
__device__ float g_XK[ELEMS];
__device__ float g_scan[ELEMS];
__device__ float g_lr[BZ*NHD*NMBC*MBSZ];
__device__ float g_lrraw[8192 * 32];
__device__ __half g_A_hf[(size_t)8192 * KP];     // [hi | lo]
__device__ __half g_B_hf[(size_t)NROWS_B * KP];  // [hi | hi]

// ---------------- PTX helpers ----------------
__device__ __forceinline__ uint32_t smem_u32(const void* p) {
    uint32_t a;
    asm("{ .reg .u64 t; cvta.to.shared.u64 t, %1; cvt.u32.u64 %0, t; }" : "=r"(a) : "l"(p));
    return a;
}
#define CPA16(d, s) asm volatile("cp.async.cg.shared.global [%0], [%1], 16;" :: "r"(d), "l"(s) : "memory")

__device__ __forceinline__ void ldsm_x4(uint32_t a, uint32_t& r0, uint32_t& r1, uint32_t& r2, uint32_t& r3) {
    asm volatile("ldmatrix.sync.aligned.m8n8.x4.shared.b16 {%0,%1,%2,%3}, [%4];"
                 : "=r"(r0), "=r"(r1), "=r"(r2), "=r"(r3) : "r"(a));
}
__device__ __forceinline__ void mma_f16(float* c, const uint32_t* a, const uint32_t* b) {
    asm volatile("mma.sync.aligned.m16n8k16.row.col.f32.f16.f16.f32 "
                 "{%0,%1,%2,%3}, {%4,%5,%6,%7}, {%8,%9}, {%0,%1,%2,%3};"
                 : "+f"(c[0]), "+f"(c[1]), "+f"(c[2]), "+f"(c[3])
                 : "r"(a[0]), "r"(a[1]), "r"(a[2]), "r"(a[3]), "r"(b[0]), "r"(b[1]));
}

// ---------------- split-fp16 helpers ----------------
__device__ __forceinline__ void splitf16(const float4& v, uint2& hi, uint2& lo) {
    __half2 h01 = __floats2half2_rn(v.x, v.y);
    __half2 h23 = __floats2half2_rn(v.z, v.w);
    float2 f01 = __half22float2(h01), f23 = __half22float2(h23);
    __half2 l01 = __floats2half2_rn(v.x - f01.x, v.y - f01.y);
    __half2 l23 = __floats2half2_rn(v.z - f23.x, v.w - f23.y);
    hi.x = *(uint32_t*)&h01; hi.y = *(uint32_t*)&h23;
    lo.x = *(uint32_t*)&l01; lo.y = *(uint32_t*)&l23;
}

// ---------------- A conversion ----------------
__global__ __launch_bounds__(256) void ttt_cvtA(const float* __restrict__ src)
{
    int t = blockIdx.x * 256 + threadIdx.x;
    float4 v = ((const float4*)src)[t];
    int r = t >> 9, c4 = t & 511;
    size_t base = (size_t)r * KP + (c4 << 2);
    uint2 hi, lo;
    splitf16(v, hi, lo);
    *(uint2*)(g_A_hf + base)        = hi;
    *(uint2*)(g_A_hf + base + 2048) = lo;
}

// ---------------- B conversion (3 sources + zero pad) ----------------
__global__ __launch_bounds__(256) void ttt_cvtB(const float* __restrict__ w0,
                                                const float* __restrict__ w1,
                                                const float* __restrict__ w2)
{
    int row = blockIdx.x >> 1;
    int half = blockIdx.x & 1;
    int tid = threadIdx.x;
    const float* srcp = nullptr;
    if (row < 2048) srcp = w0 + (size_t)row * 2048;
    else if (row < 4096) srcp = w1 + (size_t)(row - 2048) * 2048;
    else if (row < 4128) srcp = w2 + (size_t)(row - 4096) * 2048;
    float4 v = make_float4(0, 0, 0, 0);
    if (srcp) v = ((const float4*)srcp)[half * 256 + tid];
    size_t base = (size_t)row * KP + ((half * 256 + tid) << 2);
    uint2 hi, lo;
    splitf16(v, hi, lo);
    *(uint2*)(g_B_hf + base)        = hi;
    *(uint2*)(g_B_hf + base + 2048) = hi;
}

// ---------------- fp16 mma.sync GEMM, 3-stage cp.async pipeline ----------------
#define HS_STAGE 32768
__global__ __launch_bounds__(256) void ttt_hgemm(float* Cext, int fused)
{
    extern __shared__ char smem[];
    uint32_t sb = smem_u32(smem);
    const int tid = threadIdx.x;
    const int wid = tid >> 5, lane = tid & 31;
    const int m0 = blockIdx.y << 7;
    const int n0 = blockIdx.x << 7;
    const int mw = (wid >> 2) << 6;
    const int nw = (wid & 3) << 5;

    const __half* Ab = g_A_hf + (size_t)m0 * KP;
    const __half* Bb = g_B_hf + (size_t)n0 * KP;

    float acc[4][4][4];
#pragma unroll
    for (int i = 0; i < 4; i++)
#pragma unroll
        for (int j = 0; j < 4; j++)
#pragma unroll
            for (int q = 0; q < 4; q++) acc[i][j][q] = 0.0f;

    auto load_stage = [&](int s, int kt) {
        uint32_t sA = sb + s * HS_STAGE;
        uint32_t sB = sA + 16384;
#pragma unroll
        for (int i = 0; i < 4; i++) {
            int ck = tid + (i << 8);
            int row = ck >> 3, c = ck & 7;
            uint32_t soff = (uint32_t)(row << 7) + (((uint32_t)(c ^ (row & 7))) << 4);
            CPA16(sA + soff, (const char*)(Ab + (size_t)row * KP + kt * 64 + c * 8));
            CPA16(sB + soff, (const char*)(Bb + (size_t)row * KP + kt * 64 + c * 8));
        }
        asm volatile("cp.async.commit_group;" ::: "memory");
    };

    load_stage(0, 0);
    load_stage(1, 1);
    const int lr15 = lane & 15, lhi = lane >> 4;

    for (int kt = 0; kt < KTILES; kt++) {
        int s = kt % 3;
        if (kt < KTILES - 2) {
            asm volatile("cp.async.wait_group 1;" ::: "memory");
        } else {
            asm volatile("cp.async.wait_group 0;" ::: "memory");
        }
        __syncthreads();
        if (kt + 2 < KTILES) load_stage((kt + 2) % 3, kt + 2);

        uint32_t aBase = sb + s * HS_STAGE;
        uint32_t bBase = aBase + 16384;
#pragma unroll
        for (int ks = 0; ks < 4; ks++) {
            uint32_t af[4][4];
#pragma unroll
            for (int mt = 0; mt < 4; mt++) {
                int row = mw + mt * 16 + lr15;
                uint32_t ad = aBase + (row << 7) + ((uint32_t)((2 * ks + lhi) ^ (row & 7)) << 4);
                ldsm_x4(ad, af[mt][0], af[mt][1], af[mt][2], af[mt][3]);
            }
            uint32_t bf[4][2];
#pragma unroll
            for (int np = 0; np < 2; np++) {
                int row = nw + np * 16 + lr15;
                uint32_t bd = bBase + (row << 7) + ((uint32_t)((2 * ks + lhi) ^ (row & 7)) << 4);
                uint32_t r0, r1, r2, r3;
                ldsm_x4(bd, r0, r1, r2, r3);
                bf[np * 2][0] = r0;     bf[np * 2][1] = r2;
                bf[np * 2 + 1][0] = r1; bf[np * 2 + 1][1] = r3;
            }
#pragma unroll
            for (int mt = 0; mt < 4; mt++)
#pragma unroll
                for (int nt = 0; nt < 4; nt++)
                    mma_f16(acc[mt][nt], af[mt], bf[nt]);
        }
        __syncthreads();
    }

#pragma unroll
    for (int mt = 0; mt < 4; mt++) {
#pragma unroll
        for (int nt = 0; nt < 4; nt++) {
            int col = n0 + nw + nt * 8 + (lane & 3) * 2;
            int row = m0 + mw + mt * 16 + (lane >> 2);
            float2 va = make_float2(acc[mt][nt][0], acc[mt][nt][1]);
            float2 vb = make_float2(acc[mt][nt][2], acc[mt][nt][3]);
            if (!fused) {
                *(float2*)(Cext + (size_t)row * 2048 + col) = va;
                *(float2*)(Cext + (size_t)(row + 8) * 2048 + col) = vb;
            } else if (col < 2048) {
                *(float2*)(g_xq + (size_t)row * 2048 + col) = va;
                *(float2*)(g_xq + (size_t)(row + 8) * 2048 + col) = vb;
            } else if (col < 4096) {
                *(float2*)(g_xv + (size_t)row * 2048 + col - 2048) = va;
                *(float2*)(g_xv + (size_t)(row + 8) * 2048 + col - 2048) = vb;
            } else if (col < 4128) {
                *(float2*)(g_lrraw + (size_t)row * 32 + col - 4096) = va;
                *(float2*)(g_lrraw + (size_t)(row + 8) * 32 + col - 4096) = vb;
            }
        }
    }
}

// ---------------- lr sigmoid + relayout ----------------
__global__ __launch_bounds__(256) void ttt_lr_sig(const float* __restrict__ lrb)
{
    int idx = blockIdx.x * 256 + threadIdx.x;
    int bl = idx >> 5, h = idx & 31;
    float v = g_lrraw[idx];
    float sg = 1.0f / (1.0f + expf(-(v + lrb[h])));
    int b = bl >> 11, l = bl & (LZ - 1);
    g_lr[(((size_t)b * NHD + h) * NMBC + (l >> 4)) * MBSZ + (l & 15)] = sg * (1.0f / 64.0f);
}

// ---------------- causal dwconv + RoPE (vectorized weights, uniform l) ----------------
__global__ __launch_bounds__(256) void ttt_conv_rope(
    const float* __restrict__ cqw, const float* __restrict__ cqb,
    const float* __restrict__ ckw, const float* __restrict__ ckb)
{
    __shared__ float scs[32], ssn[32];
    int idx = blockIdx.x * 256 + threadIdx.x;
    int pr = idx & (WD / 2 - 1);
    int bl = idx >> 10;
    int l  = bl & (LZ - 1);
    int ch = pr * 2;

    if (threadIdx.x < 32) {
        float fr = (float)(l & 15) * exp2f(-(float)threadIdx.x * (13.2877123795f / 32.0f));
        sincosf(fr, &ssn[threadIdx.x], &scs[threadIdx.x]);
    }
    __syncthreads();

    float4 wq0 = ((const float4*)cqw)[ch];
    float4 wq1 = ((const float4*)cqw)[ch + 1];
    float4 wk0 = ((const float4*)ckw)[ch];
    float4 wk1 = ((const float4*)ckw)[ch + 1];
    float2 bq = ((const float2*)cqb)[pr];
    float2 bk = ((const float2*)ckb)[pr];

    const float2* xin = (const float2*)g_xq;
    float q0 = bq.x, q1 = bq.y, k0 = bk.x, k1 = bk.y;
    if (l >= 3) {   // block-uniform branch
        float2 v0 = xin[(size_t)(bl - 3) * (WD / 2) + pr];
        float2 v1 = xin[(size_t)(bl - 2) * (WD / 2) + pr];
        float2 v2 = xin[(size_t)(bl - 1) * (WD / 2) + pr];
        float2 v3 = xin[(size_t)bl * (WD / 2) + pr];
        q0 += v0.x * wq0.x + v1.x * wq0.y + v2.x * wq0.z + v3.x * wq0.w;
        q1 += v0.y * wq1.x + v1.y * wq1.y + v2.y * wq1.z + v3.y * wq1.w;
        k0 += v0.x * wk0.x + v1.x * wk0.y + v2.x * wk0.z + v3.x * wk0.w;
        k1 += v0.y * wk1.x + v1.y * wk1.y + v2.y * wk1.z + v3.y * wk1.w;
    } else {
        const float* wq0a = (const float*)&wq0;
        const float* wq1a = (const float*)&wq1;
        const float* wk0a = (const float*)&wk0;
        const float* wk1a = (const float*)&wk1;
#pragma unroll
        for (int k = 0; k < 4; k++) {
            if (l - 3 + k >= 0) {
                float2 v = xin[(size_t)(bl - 3 + k) * (WD / 2) + pr];
                q0 += v.x * wq0a[k];  q1 += v.y * wq1a[k];
                k0 += v.x * wk0a[k];  k1 += v.y * wk1a[k];
            }
        }
    }
    int i = (ch & 63) >> 1;
    float sn = ssn[i], cs = scs[i];
    ((float2*)g_XQ)[idx] = make_float2(q0 * cs - q1 * sn, q1 * cs + q0 * sn);
    ((float2*)g_XK)[idx] = make_float2(k0 * cs - k1 * sn, k1 * cs + k0 * sn);
}

// ---------------- the TTT scan: one block (256 threads) per (b,h) ----------------
__global__ __launch_bounds__(256) void ttt_scan_kernel(
    const float* __restrict__ lt_idx,
    const float* __restrict__ lnw_g, const float* __restrict__ lnb_g,
    const float* __restrict__ W1g,   const float* __restrict__ b1g)
{
    __shared__ float W1[64][64];
    __shared__ float sxq[16][68], sxk[16][68], sxv[16][68];
    __shared__ float grad[16][68], z[16][68];
    __shared__ float attn[16][16];
    __shared__ float b1[64], lnw[64], lnb[64], lr[16], tok[16];

    int tid = threadIdx.x;
    int b = blockIdx.x >> 5, h = blockIdx.x & 31;

    for (int o = tid; o < 4096; o += 256)
        ((float*)W1)[o] = W1g[(size_t)h * 4096 + o];
    if (tid < 64) {
        b1[tid]  = b1g[h * 64 + tid];
        lnw[tid] = lnw_g[h * 64 + tid];
        lnb[tid] = lnb_g[h * 64 + tid];
    }
    if (tid < 16) tok[tid] = fmaxf(1.0f / (float)(tid + 1) + lt_idx[tid], 0.0f);
    __syncthreads();

    const int warp = tid >> 5, lane = tid & 31;
    const int ii = tid >> 4;
    const int d0 = (tid & 15) * 4;
    const size_t base = ((size_t)b * LZ) * WD + (size_t)h * HDM;

    for (int n = 0; n < NMBC; n++) {
        {
            size_t g0 = base + (size_t)(n * MBSZ + ii) * WD + d0;
            *(float4*)&sxq[ii][d0] = *(const float4*)&g_XQ[g0];
            *(float4*)&sxk[ii][d0] = *(const float4*)&g_XK[g0];
            *(float4*)&sxv[ii][d0] = *(const float4*)&g_xv[g0];
        }
        if (tid < 16) lr[tid] = g_lr[(((size_t)b * NHD + h) * NMBC + n) * MBSZ + tid];
        __syncthreads();

        {
            float4 acc = *(const float4*)&b1[d0];
#pragma unroll 8
            for (int e = 0; e < 64; e++) {
                float xe = sxk[ii][e];
                float4 w = *(const float4*)&W1[e][d0];
                acc.x += xe * w.x; acc.y += xe * w.y; acc.z += xe * w.z; acc.w += xe * w.w;
            }
            *(float4*)&z[ii][d0] = acc;
        }
        {
            int i = tid >> 4, j = tid & 15;
            float s = 0.0f;
#pragma unroll 8
            for (int d = 0; d < 64; d++) s += sxq[i][d] * sxk[j][d];
            attn[i][j] = s;
        }
        __syncthreads();

        {
#pragma unroll
            for (int rr = 0; rr < 2; rr++) {
                int r = warp * 2 + rr;
                float x0 = z[r][lane], x1 = z[r][lane + 32];
                float s = x0 + x1;
#pragma unroll
                for (int o = 16; o; o >>= 1) s += __shfl_xor_sync(0xffffffffu, s, o);
                float mu = s * (1.0f / 64.0f);
                float e0 = x0 - mu, e1 = x1 - mu;
                float v = e0 * e0 + e1 * e1;
#pragma unroll
                for (int o = 16; o; o >>= 1) v += __shfl_xor_sync(0xffffffffu, v, o);
                float rstd = rsqrtf(v * (1.0f / 64.0f) + EPSC);
                float xh0 = e0 * rstd, xh1 = e1 * rstd;
                float t0 = sxv[r][lane] - sxk[r][lane];
                float t1 = sxv[r][lane + 32] - sxk[r][lane + 32];
                float gy0 = (lnw[lane] * xh0 + lnb[lane] - t0) * lnw[lane];
                float gy1 = (lnw[lane + 32] * xh1 + lnb[lane + 32] - t1) * lnw[lane + 32];
                float s1 = gy0 + gy1, s2 = gy0 * xh0 + gy1 * xh1;
#pragma unroll
                for (int o = 16; o; o >>= 1) {
                    s1 += __shfl_xor_sync(0xffffffffu, s1, o);
                    s2 += __shfl_xor_sync(0xffffffffu, s2, o);
                }
                float sc = rstd * (1.0f / 64.0f);
                grad[r][lane]      = (64.0f * gy0 - s1 - xh0 * s2) * sc;
                grad[r][lane + 32] = (64.0f * gy1 - s1 - xh1 * s2) * sc;
            }
        }
        __syncthreads();

        {
            float4 acc = *(const float4*)&b1[d0];
#pragma unroll 8
            for (int e = 0; e < 64; e++) {
                float xe = sxq[ii][e];
                float4 w = *(const float4*)&W1[e][d0];
                acc.x += xe * w.x; acc.y += xe * w.y; acc.z += xe * w.z; acc.w += xe * w.w;
            }
            float tk = tok[ii];
            for (int j = 0; j <= ii; j++) {
                float cf = tk * lr[j] * (attn[ii][j] + 1.0f);
                float4 gr = *(const float4*)&grad[j][d0];
                acc.x -= cf * gr.x; acc.y -= cf * gr.y; acc.z -= cf * gr.z; acc.w -= cf * gr.w;
            }
            *(float4*)&z[ii][d0] = acc;
        }
        __syncthreads();

        {
#pragma unroll
            for (int rr = 0; rr < 2; rr++) {
                int r = warp * 2 + rr;
                float x0 = z[r][lane], x1 = z[r][lane + 32];
                float s = x0 + x1;
#pragma unroll
                for (int o = 16; o; o >>= 1) s += __shfl_xor_sync(0xffffffffu, s, o);
                float mu = s * (1.0f / 64.0f);
                float e0 = x0 - mu, e1 = x1 - mu;
                float v = e0 * e0 + e1 * e1;
#pragma unroll
                for (int o = 16; o; o >>= 1) v += __shfl_xor_sync(0xffffffffu, v, o);
                float rstd = rsqrtf(v * (1.0f / 64.0f) + EPSC);
                size_t go = base + (size_t)(n * MBSZ + r) * WD;
                g_scan[go + lane]      = sxq[r][lane]      + lnw[lane] * (e0 * rstd)      + lnb[lane];
                g_scan[go + lane + 32] = sxq[r][lane + 32] + lnw[lane + 32] * (e1 * rstd) + lnb[lane + 32];
            }
        }

        {
            float te = tok[15];
#pragma unroll
            for (int p = 0; p < 4; p++) {
                int d = ii * 4 + p;
                float4 acc = *(const float4*)&W1[d][d0];
#pragma unroll
                for (int j = 0; j < 16; j++) {
                    float cf = te * lr[j] * sxk[j][d];
                    float4 gr = *(const float4*)&grad[j][d0];
                    acc.x -= cf * gr.x; acc.y -= cf * gr.y; acc.z -= cf * gr.z; acc.w -= cf * gr.w;
                }
                *(float4*)&W1[d][d0] = acc;
            }
            if (tid < 64) {
                float s = 0.0f;
#pragma unroll
                for (int j = 0; j < 16; j++) s += lr[j] * grad[j][tid];
                b1[tid] -= te * s;
            }
        }
        __syncthreads();
    }
}

// ---------------- post layer-norm fused with A split-fp16 conversion ----------------
__global__ __launch_bounds__(256) void ttt_postnorm_cvt(
    const float* __restrict__ pw, const float* __restrict__ pb)
{
    __shared__ float red[8];
    int bl = blockIdx.x, tid = threadIdx.x;
    int lane = tid & 31, warp = tid >> 5;
    const float4* src = (const float4*)(g_scan + (size_t)bl * WD);
    float4 v0 = src[tid], v1 = src[tid + 256];

    float s = v0.x + v0.y + v0.z + v0.w + v1.x + v1.y + v1.z + v1.w;
#pragma unroll
    for (int o = 16; o; o >>= 1) s += __shfl_xor_sync(0xffffffffu, s, o);
    if (lane == 0) red[warp] = s;
    __syncthreads();
    float tot = 0.0f;
#pragma unroll
    for (int i = 0; i < 8; i++) tot += red[i];
    float mu = tot * (1.0f / 2048.0f);
    __syncthreads();

    float q =
        (v0.x - mu) * (v0.x - mu) + (v0.y - mu) * (v0.y - mu) +
        (v0.z - mu) * (v0.z - mu) + (v0.w - mu) * (v0.w - mu) +
        (v1.x - mu) * (v1.x - mu) + (v1.y - mu) * (v1.y - mu) +
        (v1.z - mu) * (v1.z - mu) + (v1.w - mu) * (v1.w - mu);
#pragma unroll
    for (int o = 16; o; o >>= 1) q += __shfl_xor_sync(0xffffffffu, q, o);
    if (lane == 0) red[warp] = q;
    __syncthreads();
    float qt = 0.0f;
#pragma unroll
    for (int i = 0; i < 8; i++) qt += red[i];
    float rstd = rsqrtf(qt * (1.0f / 2048.0f) + EPSC);

    float4 w0 = ((const float4*)pw)[tid], w1 = ((const float4*)pw)[tid + 256];
    float4 b0 = ((const float4*)pb)[tid], b1v = ((const float4*)pb)[tid + 256];
    float4 o0, o1;
    o0.x = (v0.x - mu) * rstd * w0.x + b0.x;
    o0.y = (v0.y - mu) * rstd * w0.y + b0.y;
    o0.z = (v0.z - mu) * rstd * w0.z + b0.z;
    o0.w = (v0.w - mu) * rstd * w0.w + b0.w;
    o1.x = (v1.x - mu) * rstd * w1.x + b1v.x;
    o1.y = (v1.y - mu) * rstd * w1.y + b1v.y;
    o1.z = (v1.z - mu) * rstd * w1.z + b1v.z;
    o1.w = (v1.w - mu) * rstd * w1.w + b1v.w;

    size_t base0 = (size_t)bl * KP + (tid << 2);
    size_t base1 = (size_t)bl * KP + ((tid + 256) << 2);
    uint2 hi, lo;
    splitf16(o0, hi, lo);
    *(uint2*)(g_A_hf + base0)        = hi;
    *(uint2*)(g_A_hf + base0 + 2048) = lo;
    splitf16(o1, hi, lo);
    *(uint2*)(g_A_hf + base1)        = hi;
    *(uint2*)(g_A_hf + base1 + 2048) = lo;
}

// ---------------- launcher ----------------
extern "C" void kernel_launch(void* const* d_in, const int* in_sizes, int n_in,
                              void* d_out, int out_size)
{
    const float* hs  = (const float*)d_in[0];
    const float* q_w = (const float*)d_in[1];
    const float* v_w = (const float*)d_in[2];
    const float* o_w = (const float*)d_in[3];
    const float* cqw = (const float*)d_in[4];
    const float* cqb = (const float*)d_in[5];
    const float* ckw = (const float*)d_in[6];
    const float* ckb = (const float*)d_in[7];
    const float* lrw = (const float*)d_in[8];
    const float* lrb = (const float*)d_in[9];
    const float* lti = (const float*)d_in[10];
    const float* tnw = (const float*)d_in[11];
    const float* tnb = (const float*)d_in[12];
    const float* W1i = (const float*)d_in[13];
    const float* b1i = (const float*)d_in[14];
    const float* pnw = (const float*)d_in[15];
    const float* pnb = (const float*)d_in[16];
    float* out = (float*)d_out;

    static int smem_set = 0;
    if (!smem_set) {
        cudaFuncSetAttribute(ttt_hgemm, cudaFuncAttributeMaxDynamicSharedMemorySize, 3 * HS_STAGE);
        smem_set = 1;
    }

    // fused QV+lr projection: A=hs, B=[q_w; v_w; lr_w; pad]
    ttt_cvtA<<<16384, 256>>>(hs);
    ttt_cvtB<<<2 * NROWS_B, 256>>>(q_w, v_w, lrw);
    ttt_hgemm<<<dim3(33, 64), 256, 3 * HS_STAGE>>>(nullptr, 1);   // -> g_xq, g_xv, g_lrraw

    ttt_conv_rope<<<(ELEMS / 2) / 256, 256>>>(cqw, cqb, ckw, ckb);
    ttt_lr_sig<<<1024, 256>>>(lrb);
    ttt_scan_kernel<<<BZ * NHD, 256>>>(lti, tnw, tnb, W1i, b1i);

    // B for final GEMM (stream-ordered after GEMM1 read g_B_hf)
    ttt_cvtB<<<2 * 2048, 256>>>(o_w, o_w, o_w);
    ttt_postnorm_cvt<<<BZ * LZ, 256>>>(pnw, pnb);                 // -> g_A_hf

    ttt_hgemm<<<dim3(16, 64), 256, 3 * HS_STAGE>>>(out, 0);
}